// round 13
// baseline (speedup 1.0000x reference)
#include <cuda_runtime.h>
#include <cuda_bf16.h>
#include <cstdint>

#define CDIM 128
#define NS1 74
#define PQ 72   // bf16 tile pitch (144B)
#define PQA 40  // bf16 tile pitch (80B)

__device__ float g_part[2][80][64][CDIM];   // 5.2 MB
__device__ float g_UV[2][64][CDIM];
__device__ unsigned short g_Ph[64][128], g_Pl[64][128];
__device__ unsigned short g_Rh[64][128], g_Rl[64][128];
__device__ unsigned short g_Sh[64][128], g_Sl[64][128];   // S = P - R

// ---------------------------------------------------------------------------
// helpers
// ---------------------------------------------------------------------------
__device__ __forceinline__ unsigned sadr(const void* p) {
    return (unsigned)__cvta_generic_to_shared(p);
}
__device__ __forceinline__ uint32_t pk2(float x0, float x1) {
    uint32_t d;
    asm("cvt.rn.bf16x2.f32 %0, %2, %1;" : "=r"(d) : "f"(x0), "f"(x1));
    return d;
}
__device__ __forceinline__ float bfr(float x) {
    return __bfloat162float(__float2bfloat16(x));
}
__device__ __forceinline__ void cvst(unsigned short* hp, unsigned short* lp, float4 a) {
    ((uint32_t*)hp)[0] = pk2(a.x, a.y);
    ((uint32_t*)hp)[1] = pk2(a.z, a.w);
    float l0 = a.x - bfr(a.x), l1 = a.y - bfr(a.y);
    float l2 = a.z - bfr(a.z), l3 = a.w - bfr(a.w);
    ((uint32_t*)lp)[0] = pk2(l0, l1);
    ((uint32_t*)lp)[1] = pk2(l2, l3);
}
__device__ __forceinline__ float4 add4(float4 a, float4 b) {
    return make_float4(a.x + b.x, a.y + b.y, a.z + b.z, a.w + b.w);
}
__device__ __forceinline__ float4 sub4(float4 a, float4 b) {
    return make_float4(a.x - b.x, a.y - b.y, a.z - b.z, a.w - b.w);
}
__device__ __forceinline__ void ldmA(uint32_t* a, unsigned addr) {
    asm volatile("ldmatrix.sync.aligned.m8n8.x4.shared.b16 {%0,%1,%2,%3},[%4];"
        : "=r"(a[0]), "=r"(a[1]), "=r"(a[2]), "=r"(a[3]) : "r"(addr));
}
__device__ __forceinline__ void ldmAT(uint32_t* a, unsigned addr) {
    asm volatile("ldmatrix.sync.aligned.m8n8.x4.trans.shared.b16 {%0,%1,%2,%3},[%4];"
        : "=r"(a[0]), "=r"(a[1]), "=r"(a[2]), "=r"(a[3]) : "r"(addr));
}
__device__ __forceinline__ void ldmBT(uint32_t* b, unsigned addr) {
    asm volatile("ldmatrix.sync.aligned.m8n8.x2.trans.shared.b16 {%0,%1},[%2];"
        : "=r"(b[0]), "=r"(b[1]) : "r"(addr));
}
__device__ __forceinline__ void mma(float* d, const uint32_t* a, const uint32_t* b) {
    asm volatile("mma.sync.aligned.m16n8k16.row.col.f32.bf16.bf16.f32 "
        "{%0,%1,%2,%3},{%4,%5,%6,%7},{%8,%9},{%0,%1,%2,%3};"
        : "+f"(d[0]), "+f"(d[1]), "+f"(d[2]), "+f"(d[3])
        : "r"(a[0]), "r"(a[1]), "r"(a[2]), "r"(a[3]), "r"(b[0]), "r"(b[1]));
}

// ---------------------------------------------------------------------------
// Kernel 1: U/V partials (Karatsuba 9-term), chunk loop + register prefetch.
//   m1 = Qr^T re, m2 = Qi^T im, m3 = (Qr+Qi)^T (re-im)
//   U = m1 + m2 ; V = m3 - m1 + m2
// grid (74, 2 c-halves), block 256: 8 warps = 4 k-slabs(16) x 2 c-sub(32).
// ---------------------------------------------------------------------------
__global__ __launch_bounds__(256, 1) void k1_partial(
    const float* __restrict__ Qr, const float* __restrict__ Qi,
    const float* __restrict__ re, const float* __restrict__ im, int N)
{
    __shared__ unsigned short sQrh[32][PQ], sQrl[32][PQ];
    __shared__ unsigned short sQih[32][PQ], sQil[32][PQ];
    __shared__ unsigned short sQsh[32][PQ], sQsl[32][PQ];
    __shared__ unsigned short sReh[32][PQ], sRel[32][PQ];
    __shared__ unsigned short sImh[32][PQ], sIml[32][PQ];
    __shared__ unsigned short sDh [32][PQ], sDl [32][PQ];

    const int s  = blockIdx.x;
    const int c0 = blockIdx.y * 64;
    const int tid = threadIdx.x;
    const int nchunks = (N + 31) >> 5;
    const float4 f4z = make_float4(0.f, 0.f, 0.f, 0.f);

    const int lane = tid & 31, warp = tid >> 5;
    const int m0 = (warp & 3) * 16;
    const int cs = (warp >> 2) * 32;
    const int r8 = lane & 7, sel = lane >> 3;
    const int atrow = ((sel >> 1) & 1) * 8 + r8;
    const int atcol = m0 + (sel & 1) * 8;
    const int brow = lane & 15;
    const int gid = lane >> 2, tig = lane & 3;

    float m1[4][4] = {};
    float m2[4][4] = {};
    float m3[4][4] = {};

    float4 qa[2], qb[2], xa[2], xb[2];
    auto ldchunk = [&](int ci) {
        #pragma unroll
        for (int q = 0; q < 2; q++) {
            int f = tid + 256 * q;
            int row = f >> 4, k4 = (f & 15) * 4;
            int n = ci * 32 + row;
            bool ok = (n < N);
            qa[q] = ok ? *(const float4*)(Qr + (long)n * 64 + k4) : f4z;
            qb[q] = ok ? *(const float4*)(Qi + (long)n * 64 + k4) : f4z;
            xa[q] = ok ? *(const float4*)(re + (long)n * 128 + c0 + k4) : f4z;
            xb[q] = ok ? *(const float4*)(im + (long)n * 128 + c0 + k4) : f4z;
        }
    };

    ldchunk(s);
    for (int t = 0;; t++) {
        int ci = s + t * NS1;
        if (ci >= nchunks) break;
        #pragma unroll
        for (int q = 0; q < 2; q++) {
            int f = tid + 256 * q;
            int row = f >> 4, k4 = (f & 15) * 4;
            cvst(&sQrh[row][k4], &sQrl[row][k4], qa[q]);
            cvst(&sQih[row][k4], &sQil[row][k4], qb[q]);
            cvst(&sQsh[row][k4], &sQsl[row][k4], add4(qa[q], qb[q]));
            cvst(&sReh[row][k4], &sRel[row][k4], xa[q]);
            cvst(&sImh[row][k4], &sIml[row][k4], xb[q]);
            cvst(&sDh [row][k4], &sDl [row][k4], sub4(xa[q], xb[q]));
        }
        __syncthreads();
        int cin = ci + NS1;
        if (cin < nchunks) ldchunk(cin);       // prefetch under MMA

        #pragma unroll
        for (int ks = 0; ks < 2; ks++) {
            const int n0k = ks * 16;
            uint32_t qrh[4], qrl[4], qih[4], qil[4], qsh[4], qsl[4];
            ldmAT(qrh, sadr(&sQrh[n0k + atrow][atcol]));
            ldmAT(qrl, sadr(&sQrl[n0k + atrow][atcol]));
            ldmAT(qih, sadr(&sQih[n0k + atrow][atcol]));
            ldmAT(qil, sadr(&sQil[n0k + atrow][atcol]));
            ldmAT(qsh, sadr(&sQsh[n0k + atrow][atcol]));
            ldmAT(qsl, sadr(&sQsl[n0k + atrow][atcol]));
            #pragma unroll
            for (int nt = 0; nt < 4; nt++) {
                uint32_t eh[2], el[2], fh[2], fl[2], dh[2], dl[2];
                ldmBT(eh, sadr(&sReh[n0k + brow][cs + nt * 8]));
                ldmBT(el, sadr(&sRel[n0k + brow][cs + nt * 8]));
                ldmBT(fh, sadr(&sImh[n0k + brow][cs + nt * 8]));
                ldmBT(fl, sadr(&sIml[n0k + brow][cs + nt * 8]));
                ldmBT(dh, sadr(&sDh [n0k + brow][cs + nt * 8]));
                ldmBT(dl, sadr(&sDl [n0k + brow][cs + nt * 8]));
                mma(m1[nt], qrh, eh); mma(m1[nt], qrh, el); mma(m1[nt], qrl, eh);
                mma(m2[nt], qih, fh); mma(m2[nt], qih, fl); mma(m2[nt], qil, fh);
                mma(m3[nt], qsh, dh); mma(m3[nt], qsh, dl); mma(m3[nt], qsl, dh);
            }
        }
        __syncthreads();
    }

    #pragma unroll
    for (int nt = 0; nt < 4; nt++) {
        int k = m0 + gid;
        int c = c0 + cs + nt * 8 + tig * 2;
        #pragma unroll
        for (int h = 0; h < 2; h++) {          // two row-groups of the tile
            float u0 = m1[nt][2*h+0] + m2[nt][2*h+0];
            float u1 = m1[nt][2*h+1] + m2[nt][2*h+1];
            float v0 = m3[nt][2*h+0] - m1[nt][2*h+0] + m2[nt][2*h+0];
            float v1 = m3[nt][2*h+1] - m1[nt][2*h+1] + m2[nt][2*h+1];
            *(float2*)&g_part[0][s][k + 8*h][c] = make_float2(u0, u1);
            *(float2*)&g_part[1][s][k + 8*h][c] = make_float2(v0, v1);
        }
    }
}

// ---------------------------------------------------------------------------
// Kernel 2a: reduce partials over splits, scale row k by TT = Ritz[k]^ld.
// ---------------------------------------------------------------------------
__global__ __launch_bounds__(256) void k2a_reduce(
    const float* __restrict__ Ritz, const int* __restrict__ ldp, int nsplit)
{
    __shared__ float red[256];
    const int o   = threadIdx.x & 31;
    const int seg = threadIdx.x >> 5;
    const int t   = blockIdx.x * 32 + o;
    const int uv  = t >> 13;
    const int rem = t & 8191;

    const float* p = &g_part[uv][0][0][0] + rem;
    float sum = 0.f;
    for (int s2 = seg; s2 < nsplit; s2 += 8) sum += p[(long)s2 * 8192];
    red[threadIdx.x] = sum;
    __syncthreads();

    if (threadIdx.x < 32) {
        #pragma unroll
        for (int g = 1; g < 8; g++) sum += red[g * 32 + o];
        int k = rem >> 7;
        int ld = *ldp;
        float rz = Ritz[k];
        float tt = 1.f;
        for (int i = 0; i < ld; i++) tt *= rz;
        (&g_UV[0][0][0])[t] = tt * sum;
    }
}

// ---------------------------------------------------------------------------
// Kernel 2b: P = U' @ W, R = V' @ W  ([64,128]@[128,128]), both in one block
// per c'-half; emits bf16 hi/lo for P, R, and S = P - R.
// grid 2 (c'-halves), block (16,16).
// ---------------------------------------------------------------------------
__global__ __launch_bounds__(256) void k2b_pr(const float* __restrict__ W)
{
    __shared__ float sU[64 * 68];
    __shared__ float sV[64 * 68];
    __shared__ float sW[64 * 64];

    const int cp0 = blockIdx.x * 64;
    const int tx = threadIdx.x, ty = threadIdx.y;
    const int tid = ty * 16 + tx;

    float accP[4][4] = {};
    float accR[4][4] = {};

    for (int cc = 0; cc < 128; cc += 64) {
        #pragma unroll
        for (int q = 0; q < 4; q++) {
            int f   = tid + 256 * q;
            int row = f >> 4;
            int c4  = (f & 15) * 4;
            *(float4*)&sU[row * 68 + c4] = *(const float4*)&g_UV[0][row][cc + c4];
            *(float4*)&sV[row * 68 + c4] = *(const float4*)&g_UV[1][row][cc + c4];
            *(float4*)&sW[row * 64 + c4] = *(const float4*)(W + (cc + row) * 128 + cp0 + c4);
        }
        __syncthreads();

        #pragma unroll 4
        for (int r = 0; r < 64; r++) {
            float aU[4], aV[4];
            #pragma unroll
            for (int i = 0; i < 4; i++) {
                aU[i] = sU[(ty * 4 + i) * 68 + r];
                aV[i] = sV[(ty * 4 + i) * 68 + r];
            }
            float4 w4 = *(float4*)&sW[r * 64 + tx * 4];
            float wj[4] = {w4.x, w4.y, w4.z, w4.w};
            #pragma unroll
            for (int i = 0; i < 4; i++)
                #pragma unroll
                for (int j = 0; j < 4; j++) {
                    accP[i][j] += aU[i] * wj[j];
                    accR[i][j] += aV[i] * wj[j];
                }
        }
        __syncthreads();
    }

    #pragma unroll
    for (int i = 0; i < 4; i++) {
        int k = ty * 4 + i;
        int c = cp0 + tx * 4;
        float p0 = accP[i][0], p1 = accP[i][1], p2 = accP[i][2], p3 = accP[i][3];
        float r0 = accR[i][0], r1 = accR[i][1], r2 = accR[i][2], r3 = accR[i][3];
        float s0 = p0 - r0, s1 = p1 - r1, s2 = p2 - r2, s3 = p3 - r3;
        ((uint32_t*)&g_Ph[k][c])[0] = pk2(p0, p1);
        ((uint32_t*)&g_Ph[k][c])[1] = pk2(p2, p3);
        ((uint32_t*)&g_Pl[k][c])[0] = pk2(p0 - bfr(p0), p1 - bfr(p1));
        ((uint32_t*)&g_Pl[k][c])[1] = pk2(p2 - bfr(p2), p3 - bfr(p3));
        ((uint32_t*)&g_Rh[k][c])[0] = pk2(r0, r1);
        ((uint32_t*)&g_Rh[k][c])[1] = pk2(r2, r3);
        ((uint32_t*)&g_Rl[k][c])[0] = pk2(r0 - bfr(r0), r1 - bfr(r1));
        ((uint32_t*)&g_Rl[k][c])[1] = pk2(r2 - bfr(r2), r3 - bfr(r3));
        ((uint32_t*)&g_Sh[k][c])[0] = pk2(s0, s1);
        ((uint32_t*)&g_Sh[k][c])[1] = pk2(s2, s3);
        ((uint32_t*)&g_Sl[k][c])[0] = pk2(s0 - bfr(s0), s1 - bfr(s1));
        ((uint32_t*)&g_Sl[k][c])[1] = pk2(s2 - bfr(s2), s3 - bfr(s3));
    }
}

// ---------------------------------------------------------------------------
// Kernel 3: Karatsuba 9-term, masked-ReLU epilogue.
//   m1 = Qr@P, m2 = Qi@R, m3 = (Qr+Qi)@(P-R)
//   sr = m1 + m2 ; si = m3 - m1 + m2
// grid (ceil(N/128), 2 c-halves), block 256, 1 CTA/SM:
// 8 warps = 8 n-slabs(16); each warp covers the full 64-c half (8 n8-tiles).
// Two k-phases of 32 with register-prefetched B.
// ---------------------------------------------------------------------------
__global__ __launch_bounds__(256, 1) void k3_out(
    const float* __restrict__ Qr, const float* __restrict__ Qi,
    const float* __restrict__ re, const float* __restrict__ im,
    float* __restrict__ out, int N)
{
    __shared__ unsigned short sQrh[128][PQA], sQrl[128][PQA];
    __shared__ unsigned short sQih[128][PQA], sQil[128][PQA];
    __shared__ unsigned short sQsh[128][PQA], sQsl[128][PQA];
    __shared__ unsigned short sPh[32][PQ], sPl[32][PQ];
    __shared__ unsigned short sRh[32][PQ], sRl[32][PQ];
    __shared__ unsigned short sSh[32][PQ], sSl[32][PQ];

    const int n0 = blockIdx.x * 128;
    const int c0 = blockIdx.y * 64;
    const int tid = threadIdx.x;
    const float4 f4z = make_float4(0.f, 0.f, 0.f, 0.f);

    const int lane = tid & 31, warp = tid >> 5;
    const int m0 = warp * 16;                 // n-slab
    const int arow = m0 + (lane & 15);
    const int acol8 = (lane >> 4) * 8;
    const int brow = lane & 15;
    const int gid = lane >> 2, tig = lane & 3;

    float m1[8][4] = {};
    float m2[8][4] = {};
    float m3[8][4] = {};

    #pragma unroll
    for (int ph = 0; ph < 2; ph++) {
        const int kk = ph * 32;
        // reg-first loads: Q k-half (fp32) + P/R/S k-half (bf16 hi/lo)
        float4 qa[4], qb[4];
        #pragma unroll
        for (int q = 0; q < 4; q++) {
            int f = tid + 256 * q;
            int row = f >> 3, k4 = (f & 7) * 4;
            int n = n0 + row;
            bool ok = (n < N);
            qa[q] = ok ? *(const float4*)(Qr + (long)n * 64 + kk + k4) : f4z;
            qb[q] = ok ? *(const float4*)(Qi + (long)n * 64 + kk + k4) : f4z;
        }
        uint4 pv, plv, rv, rlv, sv, slv;
        {
            int row = tid >> 3, cu = tid & 7;
            pv  = *(const uint4*)&g_Ph[kk + row][c0 + cu * 8];
            plv = *(const uint4*)&g_Pl[kk + row][c0 + cu * 8];
            rv  = *(const uint4*)&g_Rh[kk + row][c0 + cu * 8];
            rlv = *(const uint4*)&g_Rl[kk + row][c0 + cu * 8];
            sv  = *(const uint4*)&g_Sh[kk + row][c0 + cu * 8];
            slv = *(const uint4*)&g_Sl[kk + row][c0 + cu * 8];
        }
        if (ph) __syncthreads();   // protect previous phase reads
        #pragma unroll
        for (int q = 0; q < 4; q++) {
            int f = tid + 256 * q;
            int row = f >> 3, k4 = (f & 7) * 4;
            cvst(&sQrh[row][k4], &sQrl[row][k4], qa[q]);
            cvst(&sQih[row][k4], &sQil[row][k4], qb[q]);
            cvst(&sQsh[row][k4], &sQsl[row][k4], add4(qa[q], qb[q]));
        }
        {
            int row = tid >> 3, cu = tid & 7;
            *(uint4*)&sPh[row][cu * 8] = pv;
            *(uint4*)&sPl[row][cu * 8] = plv;
            *(uint4*)&sRh[row][cu * 8] = rv;
            *(uint4*)&sRl[row][cu * 8] = rlv;
            *(uint4*)&sSh[row][cu * 8] = sv;
            *(uint4*)&sSl[row][cu * 8] = slv;
        }
        __syncthreads();

        #pragma unroll
        for (int ks = 0; ks < 2; ks++) {
            const int k0 = ks * 16;
            uint32_t qrh[4], qrl[4], qih[4], qil[4], qsh[4], qsl[4];
            ldmA(qrh, sadr(&sQrh[arow][k0 + acol8]));
            ldmA(qrl, sadr(&sQrl[arow][k0 + acol8]));
            ldmA(qih, sadr(&sQih[arow][k0 + acol8]));
            ldmA(qil, sadr(&sQil[arow][k0 + acol8]));
            ldmA(qsh, sadr(&sQsh[arow][k0 + acol8]));
            ldmA(qsl, sadr(&sQsl[arow][k0 + acol8]));
            #pragma unroll
            for (int nt = 0; nt < 8; nt++) {
                uint32_t pf[2], pl[2], rf[2], rl2[2], sf[2], sl2[2];
                ldmBT(pf,  sadr(&sPh[k0 + brow][nt * 8]));
                ldmBT(pl,  sadr(&sPl[k0 + brow][nt * 8]));
                ldmBT(rf,  sadr(&sRh[k0 + brow][nt * 8]));
                ldmBT(rl2, sadr(&sRl[k0 + brow][nt * 8]));
                ldmBT(sf,  sadr(&sSh[k0 + brow][nt * 8]));
                ldmBT(sl2, sadr(&sSl[k0 + brow][nt * 8]));
                mma(m1[nt], qrh, pf); mma(m1[nt], qrh, pl); mma(m1[nt], qrl, pf);
                mma(m2[nt], qih, rf); mma(m2[nt], qih, rl2); mma(m2[nt], qil, rf);
                mma(m3[nt], qsh, sf); mma(m3[nt], qsh, sl2); mma(m3[nt], qsl, sf);
            }
        }
    }

    // epilogue: sr = m1+m2, si = m3-m1+m2, masked-ReLU add
    const long NC = (long)N * 128;
    #pragma unroll
    for (int nt = 0; nt < 8; nt++) {
        int c = c0 + nt * 8 + tig * 2;
        #pragma unroll
        for (int h = 0; h < 2; h++) {
            int n = n0 + m0 + gid + 8 * h;
            if (n >= N) continue;
            long base = (long)n * 128 + c;
            float2 rvv = *(const float2*)(re + base);
            float2 ivv = *(const float2*)(im + base);
            float sr0 = m1[nt][2*h+0] + m2[nt][2*h+0];
            float sr1 = m1[nt][2*h+1] + m2[nt][2*h+1];
            float si0 = m3[nt][2*h+0] - m1[nt][2*h+0] + m2[nt][2*h+0];
            float si1 = m3[nt][2*h+1] - m1[nt][2*h+1] + m2[nt][2*h+1];
            float mk0 = (sr0 >= 0.f) ? 1.f : 0.f;
            float mk1 = (sr1 >= 0.f) ? 1.f : 0.f;
            *(float2*)(out + base)      = make_float2(rvv.x + mk0 * sr0, rvv.y + mk1 * sr1);
            *(float2*)(out + NC + base) = make_float2(ivv.x + mk0 * si0, ivv.y + mk1 * si1);
        }
    }
}

// ---------------------------------------------------------------------------
extern "C" void kernel_launch(void* const* d_in, const int* in_sizes, int n_in,
                              void* d_out, int out_size)
{
    const float* real  = (const float*)d_in[0];
    const float* imag  = (const float*)d_in[1];
    const float* Qreal = (const float*)d_in[2];
    const float* Qimag = (const float*)d_in[3];
    const float* Ritz  = (const float*)d_in[4];
    const float* W     = (const float*)d_in[5];
    const int*   ldp   = (const int*)d_in[6];
    float* out = (float*)d_out;

    int N = in_sizes[0] / CDIM;
    int nchunks = (N + 31) / 32;
    int nsplit = (nchunks < NS1) ? nchunks : NS1;

    k1_partial<<<dim3(NS1, 2), 256>>>(Qreal, Qimag, real, imag, N);
    k2a_reduce<<<512, 256>>>(Ritz, ldp, nsplit);
    k2b_pr<<<2, dim3(16, 16)>>>(W);
    k3_out<<<dim3((N + 127) / 128, 2), 256>>>(Qreal, Qimag, real, imag, out, N);
}